// round 13
// baseline (speedup 1.0000x reference)
#include <cuda_runtime.h>
#include <math.h>

#define GX 200
#define GY 200
#define GZ 20
#define NVOX (GX*GY*GZ)               // 800000
#define NCH 8
#define TOTAL_OUT (NVOX * (1 + NCH))  // 7,200,000 floats

// Vector reductions to global memory (sm_90+ PTX).
__device__ __forceinline__ void red_add_v4(float* addr, float a, float b, float c, float d) {
    asm volatile("red.global.add.v4.f32 [%0], {%1,%2,%3,%4};"
                 :: "l"(addr), "f"(a), "f"(b), "f"(c), "f"(d) : "memory");
}
__device__ __forceinline__ void red_add_v2(float* addr, float a, float b) {
    asm volatile("red.global.add.v2.f32 [%0], {%1,%2};"
                 :: "l"(addr), "f"(a), "f"(b) : "memory");
}

// One warp per Gaussian; one xy-column per lane, z walked serially in
// aligned pairs (control flow is warp-uniform: izmin/cz are per-Gaussian).
__global__ __launch_bounds__(256) void vox_kernel(
    const float* __restrict__ means, const float* __restrict__ opac,
    const float* __restrict__ scales, const float* __restrict__ rots,
    const float* __restrict__ feats,
    float* __restrict__ density, float* __restrict__ gfeat, int N)
{
    int g    = (blockIdx.x * blockDim.x + threadIdx.x) >> 5;
    int lane = threadIdx.x & 31;
    if (g >= N) return;

    // ---- per-Gaussian setup (redundant across lanes; broadcast loads) ----
    float mx = means[3*g+0], my = means[3*g+1], mz = means[3*g+2];
    float op = opac[g];
    float sx = scales[3*g+0], sy = scales[3*g+1], sz = scales[3*g+2];
    float qr = rots[4*g+0], qx = rots[4*g+1], qy = rots[4*g+2], qz = rots[4*g+3];

    float qn = rsqrtf(qr*qr + qx*qx + qy*qy + qz*qz + 1e-8f);
    qr *= qn; qx *= qn; qy *= qn; qz *= qn;

    float r00 = 1.f - 2.f*(qy*qy + qz*qz), r01 = 2.f*(qx*qy - qr*qz), r02 = 2.f*(qx*qz + qr*qy);
    float r10 = 2.f*(qx*qy + qr*qz), r11 = 1.f - 2.f*(qx*qx + qz*qz), r12 = 2.f*(qy*qz - qr*qx);
    float r20 = 2.f*(qx*qz - qr*qy), r21 = 2.f*(qy*qz + qr*qx), r22 = 1.f - 2.f*(qx*qx + qy*qy);

    float sx2 = sx*sx, sy2 = sy*sy, sz2 = sz*sz;
    // cov = R diag(s^2) R^T (symmetric)
    float c00 = r00*r00*sx2 + r01*r01*sy2 + r02*r02*sz2;
    float c01 = r00*r10*sx2 + r01*r11*sy2 + r02*r12*sz2;
    float c02 = r00*r20*sx2 + r01*r21*sy2 + r02*r22*sz2;
    float c11 = r10*r10*sx2 + r11*r11*sy2 + r12*r12*sz2;
    float c12 = r10*r20*sx2 + r11*r21*sy2 + r12*r22*sz2;
    float c22 = r20*r20*sx2 + r21*r21*sy2 + r22*r22*sz2;

    float sdx = sqrtf(c00), sdy = sqrtf(c11), sdz = sqrtf(c22);
    float bminx = mx - 3.f*sdx, bminy = my - 3.f*sdy, bminz = mz - 3.f*sdz;
    float bmaxx = mx + 3.f*sdx, bmaxy = my + 3.f*sdy, bmaxz = mz + 3.f*sdz;

    // keep mask (filter_gaussians): bbox overlaps volume, opacity above threshold
    bool keep = (bmaxx > -40.f) && (bmaxy > -40.f) && (bmaxz > -4.f)
             && (bminx <  40.f) && (bminy <  40.f) && (bminz <  4.f)
             && (op > 1e-4f);
    if (!keep) return;

    // 3x3 symmetric inverse via adjugate
    float m00 = c11*c22 - c12*c12;
    float m01 = c02*c12 - c01*c22;
    float m02 = c01*c12 - c02*c11;
    float det = c00*m00 + c01*m01 + c02*m02;
    float idet = 1.0f / det;
    float i00 = m00 * idet;
    float i01 = m01 * idet;
    float i02 = m02 * idet;
    float i11 = (c00*c22 - c02*c02) * idet;
    float i12 = (c01*c02 - c00*c12) * idet;
    float i22 = (c00*c11 - c01*c01) * idet;

    // voxel index bounds; IEEE division + trunc-toward-zero matches jnp .astype(int32)
    int ixmin = max((int)__fdiv_rn(bminx + 40.f, 0.4f), 0);
    int iymin = max((int)__fdiv_rn(bminy + 40.f, 0.4f), 0);
    int izmin = max((int)__fdiv_rn(bminz +  4.f, 0.4f), 0);
    int ixmax = min((int)__fdiv_rn(bmaxx + 40.f, 0.4f), GX - 1);
    int iymax = min((int)__fdiv_rn(bmaxy + 40.f, 0.4f), GY - 1);
    int izmax = min((int)__fdiv_rn(bmaxz +  4.f, 0.4f), GZ - 1);

    int cx = min(ixmax - ixmin + 1, 8);
    int cy = min(iymax - iymin + 1, 8);
    int cz = min(izmax - izmin + 1, 8);
    int CXY  = cx * cy;
    int zend = izmin + cz;

    // Magic reciprocal: exact c/cy = (c*mcy)>>16 for cy in [1,8], c <= 512.
    unsigned mcy = (65535u / (unsigned)cy) + 1u;

    const float4* fptr = (const float4*)(feats + 8*g);
    float4 f0 = fptr[0];
    float4 f1 = fptr[1];

    float dz_base = (float)izmin * 0.4f - 3.8f - mz;   // dz at z = izmin

    for (int c = lane; c < CXY; c += 32) {
        unsigned ox = ((unsigned)c * mcy) >> 16;       // c / cy
        int oy = c - (int)ox * cy;                     // c % cy
        int ix = ixmin + (int)ox, iy = iymin + oy;

        float dx = ((float)ix * 0.4f - 39.8f) - mx;
        float dy = ((float)iy * 0.4f - 39.8f) - my;

        // maha(z) = qc + lin*dz + i22*dz^2  (column-invariant qc, lin)
        float qc  = i00*dx*dx + 2.f*(i01*dx*dy) + i11*dy*dy;
        float lin = 2.f*(i02*dx + i12*dy);

        int   colbase = (ix * GY + iy) * GZ;
        int   z  = izmin;
        float dz = dz_base;

        // odd start: scalar emit (warp-uniform branch)
        if (z & 1) {
            float w = op * exp2f(-0.72134752f * (qc + dz*(lin + i22*dz)));
            atomicAdd(density + colbase + z, w);
            float* fp = gfeat + (size_t)(colbase + z) * NCH;
            red_add_v4(fp,     w*f0.x, w*f0.y, w*f0.z, w*f0.w);
            red_add_v4(fp + 4, w*f1.x, w*f1.y, w*f1.z, w*f1.w);
            z++; dz += 0.4f;
        }
        // aligned pairs (z even; flat parity == z parity since GZ is even)
        while (z + 1 < zend) {
            float dz1 = dz + 0.4f;
            float w0 = op * exp2f(-0.72134752f * (qc + dz *(lin + i22*dz )));
            float w1 = op * exp2f(-0.72134752f * (qc + dz1*(lin + i22*dz1)));
            int flat = colbase + z;
            red_add_v2(density + flat, w0, w1);
            float* fp = gfeat + (size_t)flat * NCH;
            red_add_v4(fp,      w0*f0.x, w0*f0.y, w0*f0.z, w0*f0.w);
            red_add_v4(fp + 4,  w0*f1.x, w0*f1.y, w0*f1.z, w0*f1.w);
            red_add_v4(fp + 8,  w1*f0.x, w1*f0.y, w1*f0.z, w1*f0.w);
            red_add_v4(fp + 12, w1*f1.x, w1*f1.y, w1*f1.z, w1*f1.w);
            z += 2; dz += 0.8f;
        }
        // tail: single leftover z (warp-uniform branch)
        if (z < zend) {
            float w = op * exp2f(-0.72134752f * (qc + dz*(lin + i22*dz)));
            atomicAdd(density + colbase + z, w);
            float* fp = gfeat + (size_t)(colbase + z) * NCH;
            red_add_v4(fp,     w*f0.x, w*f0.y, w*f0.z, w*f0.w);
            red_add_v4(fp + 4, w*f1.x, w*f1.y, w*f1.z, w*f1.w);
        }
    }
}

// One thread per HALF-voxel (one float4 of channels). Fully coalesced.
__global__ __launch_bounds__(256) void finalize_kernel(const float* __restrict__ density,
                                                        float4* __restrict__ gfeat4) {
    int i = blockIdx.x * blockDim.x + threadIdx.x;
    if (i >= NVOX * 2) return;
    float d = density[i >> 1];
    float4 v = gfeat4[i];
    float inv = 1.0f / fmaxf(d, 1e-6f);
    v.x *= inv; v.y *= inv; v.z *= inv; v.w *= inv;
    gfeat4[i] = v;
}

extern "C" void kernel_launch(void* const* d_in, const int* in_sizes, int n_in,
                              void* d_out, int out_size) {
    const float* means  = (const float*)d_in[0];
    const float* opac   = (const float*)d_in[1];
    const float* scales = (const float*)d_in[2];
    const float* rots   = (const float*)d_in[3];
    const float* feats  = (const float*)d_in[4];

    float* density = (float*)d_out;
    float* gfeat   = density + NVOX;

    int N = in_sizes[1];  // opacities: B*N*1 elements

    cudaMemsetAsync(d_out, 0, (size_t)TOTAL_OUT * sizeof(float), 0);

    int threads = N * 32;  // one warp per Gaussian
    vox_kernel<<<(threads + 255) / 256, 256>>>(means, opac, scales, rots, feats,
                                               density, gfeat, N);

    int nhalf = NVOX * 2;
    finalize_kernel<<<(nhalf + 255) / 256, 256>>>(density, (float4*)gfeat);
}

// round 15
// speedup vs baseline: 1.0536x; 1.0536x over previous
#include <cuda_runtime.h>
#include <math.h>

#define GX 200
#define GY 200
#define GZ 20
#define NVOX (GX*GY*GZ)               // 800000
#define NCH 8
#define TOTAL_OUT (NVOX * (1 + NCH))  // 7,200,000 floats
#define GPB 8                          // gaussians per block (one per warp)

// Vector float4 reduction to global memory (sm_90+ PTX).
__device__ __forceinline__ void red_add_v4(float* addr, float a, float b, float c, float d) {
    asm volatile("red.global.add.v4.f32 [%0], {%1,%2,%3,%4};"
                 :: "l"(addr), "f"(a), "f"(b), "f"(c), "f"(d) : "memory");
}

// Per-gaussian smem record (24 floats = 96B, float4-aligned at idx 16):
// [0-2] mean, [3] op, [4-9] cov-inverse (i00,i01,i02,i11,i12,i22),
// [10] bits(base), [11] bits(cnt), [12] bits(mcz), [13] bits(mcy),
// [16-23] feats
__global__ __launch_bounds__(256) void vox_kernel(
    const float* __restrict__ means, const float* __restrict__ opac,
    const float* __restrict__ scales, const float* __restrict__ rots,
    const float* __restrict__ feats,
    float* __restrict__ density, float* __restrict__ gfeat, int N)
{
    __shared__ float sp[GPB][24];

    int gbase = blockIdx.x * GPB;

    // ---- Phase 1: lanes 0..7 of warp 0 compute setup for the block's 8 gaussians ----
    if (threadIdx.x < GPB) {
        int g = gbase + threadIdx.x;
        float* r = sp[threadIdx.x];
        r[11] = __int_as_float(0);   // default: skip
        if (g < N) {
            float mx = means[3*g+0], my = means[3*g+1], mz = means[3*g+2];
            float op = opac[g];
            float sx = scales[3*g+0], sy = scales[3*g+1], sz = scales[3*g+2];
            float qr = rots[4*g+0], qx = rots[4*g+1], qy = rots[4*g+2], qz = rots[4*g+3];

            float qn = rsqrtf(qr*qr + qx*qx + qy*qy + qz*qz + 1e-8f);
            qr *= qn; qx *= qn; qy *= qn; qz *= qn;

            float r00 = 1.f - 2.f*(qy*qy + qz*qz), r01 = 2.f*(qx*qy - qr*qz), r02 = 2.f*(qx*qz + qr*qy);
            float r10 = 2.f*(qx*qy + qr*qz), r11 = 1.f - 2.f*(qx*qx + qz*qz), r12 = 2.f*(qy*qz - qr*qx);
            float r20 = 2.f*(qx*qz - qr*qy), r21 = 2.f*(qy*qz + qr*qx), r22 = 1.f - 2.f*(qx*qx + qy*qy);

            float sx2 = sx*sx, sy2 = sy*sy, sz2 = sz*sz;
            float c00 = r00*r00*sx2 + r01*r01*sy2 + r02*r02*sz2;
            float c01 = r00*r10*sx2 + r01*r11*sy2 + r02*r12*sz2;
            float c02 = r00*r20*sx2 + r01*r21*sy2 + r02*r22*sz2;
            float c11 = r10*r10*sx2 + r11*r11*sy2 + r12*r12*sz2;
            float c12 = r10*r20*sx2 + r11*r21*sy2 + r12*r22*sz2;
            float c22 = r20*r20*sx2 + r21*r21*sy2 + r22*r22*sz2;

            float sdx = sqrtf(c00), sdy = sqrtf(c11), sdz = sqrtf(c22);
            float bminx = mx - 3.f*sdx, bminy = my - 3.f*sdy, bminz = mz - 3.f*sdz;
            float bmaxx = mx + 3.f*sdx, bmaxy = my + 3.f*sdy, bmaxz = mz + 3.f*sdz;

            bool keep = (bmaxx > -40.f) && (bmaxy > -40.f) && (bmaxz > -4.f)
                     && (bminx <  40.f) && (bminy <  40.f) && (bminz <  4.f)
                     && (op > 1e-4f);
            if (keep) {
                float m00 = c11*c22 - c12*c12;
                float m01 = c02*c12 - c01*c22;
                float m02 = c01*c12 - c02*c11;
                float det = c00*m00 + c01*m01 + c02*m02;
                float idet = 1.0f / det;

                // voxel index bounds; IEEE division + trunc matches jnp int32 cast
                int ixmin = max((int)__fdiv_rn(bminx + 40.f, 0.4f), 0);
                int iymin = max((int)__fdiv_rn(bminy + 40.f, 0.4f), 0);
                int izmin = max((int)__fdiv_rn(bminz +  4.f, 0.4f), 0);
                int ixmax = min((int)__fdiv_rn(bmaxx + 40.f, 0.4f), GX - 1);
                int iymax = min((int)__fdiv_rn(bmaxy + 40.f, 0.4f), GY - 1);
                int izmax = min((int)__fdiv_rn(bmaxz +  4.f, 0.4f), GZ - 1);

                int cx = min(ixmax - ixmin + 1, 8);
                int cy = min(iymax - iymin + 1, 8);
                int cz = min(izmax - izmin + 1, 8);

                r[0] = mx; r[1] = my; r[2] = mz; r[3] = op;
                r[4] = m00 * idet;                  // i00
                r[5] = m01 * idet;                  // i01
                r[6] = m02 * idet;                  // i02
                r[7] = (c00*c22 - c02*c02) * idet;  // i11
                r[8] = (c01*c02 - c00*c12) * idet;  // i12
                r[9] = (c00*c11 - c01*c01) * idet;  // i22
                r[10] = __int_as_float(ixmin | (iymin << 8) | (izmin << 16));
                r[11] = __int_as_float(cx | (cy << 8) | (cz << 16));
                r[12] = __uint_as_float((65535u / (unsigned)cz) + 1u);  // magic for /cz
                r[13] = __uint_as_float((65535u / (unsigned)cy) + 1u);  // magic for /cy
                const float4* fptr = (const float4*)(feats + 8*g);
                *(float4*)&r[16] = fptr[0];
                *(float4*)&r[20] = fptr[1];
            }
        }
    }
    __syncthreads();

    // ---- Phase 2: warp w scatters gaussian gbase+w (proven flat-P loop) ----
    int w    = threadIdx.x >> 5;
    int lane = threadIdx.x & 31;
    const float* r = sp[w];

    int cnt = __float_as_int(r[11]);
    if (cnt == 0) return;

    float mx = r[0], my = r[1], mz = r[2], op = r[3];
    float i00 = r[4], i01 = r[5], i02 = r[6], i11 = r[7], i12 = r[8], i22 = r[9];
    int base = __float_as_int(r[10]);
    int ixmin = base & 255, iymin = (base >> 8) & 255, izmin = (base >> 16) & 255;
    int cx = cnt & 255, cy = (cnt >> 8) & 255, cz = (cnt >> 16) & 255;
    unsigned mcz = __float_as_uint(r[12]);
    unsigned mcy = __float_as_uint(r[13]);
    float4 f0 = *(const float4*)&r[16];
    float4 f1 = *(const float4*)&r[20];

    int P = cx * cy * cz;

    for (int p = lane; p < P; p += 32) {
        unsigned t  = ((unsigned)p * mcz) >> 16;   // p / cz
        int oz = p - (int)t * cz;                  // p % cz
        unsigned ox = (t * mcy) >> 16;             // t / cy
        int oy = (int)t - (int)ox * cy;            // t % cy
        int ix = ixmin + (int)ox, iy = iymin + oy, iz = izmin + oz;

        float cxp = ((float)ix * 0.4f + (-40.f)) + 0.2f;
        float cyp = ((float)iy * 0.4f + (-40.f)) + 0.2f;
        float czp = ((float)iz * 0.4f + ( -4.f)) + 0.2f;

        float dx = cxp - mx, dy = cyp - my, dz = czp - mz;
        float maha = i00*dx*dx + i11*dy*dy + i22*dz*dz
                   + 2.f*(i01*dx*dy + i02*dx*dz + i12*dy*dz);
        // exp(-0.5*maha) = exp2(-0.5*log2(e)*maha)
        float wgt = op * exp2f(-0.72134752f * maha);

        int flat = (ix * GY + iy) * GZ + iz;
        atomicAdd(density + flat, wgt);
        float* fp = gfeat + (size_t)flat * NCH;
        red_add_v4(fp,     wgt*f0.x, wgt*f0.y, wgt*f0.z, wgt*f0.w);
        red_add_v4(fp + 4, wgt*f1.x, wgt*f1.y, wgt*f1.z, wgt*f1.w);
    }
}

// One thread per HALF-voxel (one float4 of channels). Fully coalesced.
__global__ __launch_bounds__(256) void finalize_kernel(const float* __restrict__ density,
                                                        float4* __restrict__ gfeat4) {
    int i = blockIdx.x * blockDim.x + threadIdx.x;
    if (i >= NVOX * 2) return;
    float d = density[i >> 1];
    float4 v = gfeat4[i];
    float inv = 1.0f / fmaxf(d, 1e-6f);
    v.x *= inv; v.y *= inv; v.z *= inv; v.w *= inv;
    gfeat4[i] = v;
}

extern "C" void kernel_launch(void* const* d_in, const int* in_sizes, int n_in,
                              void* d_out, int out_size) {
    const float* means  = (const float*)d_in[0];
    const float* opac   = (const float*)d_in[1];
    const float* scales = (const float*)d_in[2];
    const float* rots   = (const float*)d_in[3];
    const float* feats  = (const float*)d_in[4];

    float* density = (float*)d_out;
    float* gfeat   = density + NVOX;

    int N = in_sizes[1];  // opacities: B*N*1 elements

    cudaMemsetAsync(d_out, 0, (size_t)TOTAL_OUT * sizeof(float), 0);

    int nblocks = (N + GPB - 1) / GPB;   // 8 gaussians per 256-thread block
    vox_kernel<<<nblocks, 256>>>(means, opac, scales, rots, feats, density, gfeat, N);

    int nhalf = NVOX * 2;
    finalize_kernel<<<(nhalf + 255) / 256, 256>>>(density, (float4*)gfeat);
}

// round 16
// speedup vs baseline: 1.1367x; 1.0789x over previous
#include <cuda_runtime.h>
#include <math.h>

#define GX 200
#define GY 200
#define GZ 20
#define NVOX (GX*GY*GZ)               // 800000
#define NCH 8
#define TOTAL_OUT (NVOX * (1 + NCH))  // 7,200,000 floats

// Accumulator scratch. Zero-initialized at module load; finalize_kernel
// re-zeroes it every launch, so each graph replay (and the first call)
// starts from zeros. Layout: [0,NVOX) density, [NVOX,TOTAL_OUT) gfeat.
__device__ __align__(16) float g_scr[TOTAL_OUT];

// Vector float4 reduction to global memory (sm_90+ PTX).
__device__ __forceinline__ void red_add_v4(float* addr, float a, float b, float c, float d) {
    asm volatile("red.global.add.v4.f32 [%0], {%1,%2,%3,%4};"
                 :: "l"(addr), "f"(a), "f"(b), "f"(c), "f"(d) : "memory");
}

// One warp per Gaussian (R11 proven body, accumulating into g_scr).
__global__ __launch_bounds__(256) void vox_kernel(
    const float* __restrict__ means, const float* __restrict__ opac,
    const float* __restrict__ scales, const float* __restrict__ rots,
    const float* __restrict__ feats, int N)
{
    int g    = (blockIdx.x * blockDim.x + threadIdx.x) >> 5;
    int lane = threadIdx.x & 31;
    if (g >= N) return;

    float* density = g_scr;
    float* gfeat   = g_scr + NVOX;

    // ---- per-Gaussian setup (redundant across lanes; broadcast loads) ----
    float mx = means[3*g+0], my = means[3*g+1], mz = means[3*g+2];
    float op = opac[g];
    float sx = scales[3*g+0], sy = scales[3*g+1], sz = scales[3*g+2];
    float qr = rots[4*g+0], qx = rots[4*g+1], qy = rots[4*g+2], qz = rots[4*g+3];

    float qn = rsqrtf(qr*qr + qx*qx + qy*qy + qz*qz + 1e-8f);
    qr *= qn; qx *= qn; qy *= qn; qz *= qn;

    float r00 = 1.f - 2.f*(qy*qy + qz*qz), r01 = 2.f*(qx*qy - qr*qz), r02 = 2.f*(qx*qz + qr*qy);
    float r10 = 2.f*(qx*qy + qr*qz), r11 = 1.f - 2.f*(qx*qx + qz*qz), r12 = 2.f*(qy*qz - qr*qx);
    float r20 = 2.f*(qx*qz - qr*qy), r21 = 2.f*(qy*qz + qr*qx), r22 = 1.f - 2.f*(qx*qx + qy*qy);

    float sx2 = sx*sx, sy2 = sy*sy, sz2 = sz*sz;
    // cov = R diag(s^2) R^T (symmetric)
    float c00 = r00*r00*sx2 + r01*r01*sy2 + r02*r02*sz2;
    float c01 = r00*r10*sx2 + r01*r11*sy2 + r02*r12*sz2;
    float c02 = r00*r20*sx2 + r01*r21*sy2 + r02*r22*sz2;
    float c11 = r10*r10*sx2 + r11*r11*sy2 + r12*r12*sz2;
    float c12 = r10*r20*sx2 + r11*r21*sy2 + r12*r22*sz2;
    float c22 = r20*r20*sx2 + r21*r21*sy2 + r22*r22*sz2;

    float sdx = sqrtf(c00), sdy = sqrtf(c11), sdz = sqrtf(c22);
    float bminx = mx - 3.f*sdx, bminy = my - 3.f*sdy, bminz = mz - 3.f*sdz;
    float bmaxx = mx + 3.f*sdx, bmaxy = my + 3.f*sdy, bmaxz = mz + 3.f*sdz;

    // keep mask (filter_gaussians): bbox overlaps volume, opacity above threshold
    bool keep = (bmaxx > -40.f) && (bmaxy > -40.f) && (bmaxz > -4.f)
             && (bminx <  40.f) && (bminy <  40.f) && (bminz <  4.f)
             && (op > 1e-4f);
    if (!keep) return;

    // 3x3 symmetric inverse via adjugate
    float m00 = c11*c22 - c12*c12;
    float m01 = c02*c12 - c01*c22;
    float m02 = c01*c12 - c02*c11;
    float det = c00*m00 + c01*m01 + c02*m02;
    float idet = 1.0f / det;
    float i00 = m00 * idet;
    float i01 = m01 * idet;
    float i02 = m02 * idet;
    float i11 = (c00*c22 - c02*c02) * idet;
    float i12 = (c01*c02 - c00*c12) * idet;
    float i22 = (c00*c11 - c01*c01) * idet;

    // voxel index bounds; IEEE division + trunc-toward-zero matches jnp .astype(int32)
    int ixmin = max((int)__fdiv_rn(bminx + 40.f, 0.4f), 0);
    int iymin = max((int)__fdiv_rn(bminy + 40.f, 0.4f), 0);
    int izmin = max((int)__fdiv_rn(bminz +  4.f, 0.4f), 0);
    int ixmax = min((int)__fdiv_rn(bmaxx + 40.f, 0.4f), GX - 1);
    int iymax = min((int)__fdiv_rn(bmaxy + 40.f, 0.4f), GY - 1);
    int izmax = min((int)__fdiv_rn(bmaxz +  4.f, 0.4f), GZ - 1);

    int cx = min(ixmax - ixmin + 1, 8);
    int cy = min(iymax - iymin + 1, 8);
    int cz = min(izmax - izmin + 1, 8);
    int P = cx * cy * cz;

    // Magic-number reciprocals: exact n/d = (n*m)>>16 for d in [1,8], n <= 512.
    unsigned mcz = (65535u / (unsigned)cz) + 1u;
    unsigned mcy = (65535u / (unsigned)cy) + 1u;

    const float4* fptr = (const float4*)(feats + 8*g);
    float4 f0 = fptr[0];
    float4 f1 = fptr[1];

    for (int p = lane; p < P; p += 32) {
        unsigned t  = ((unsigned)p * mcz) >> 16;   // p / cz
        int oz = p - (int)t * cz;                  // p % cz
        unsigned ox = (t * mcy) >> 16;             // t / cy
        int oy = (int)t - (int)ox * cy;            // t % cy
        int ix = ixmin + (int)ox, iy = iymin + oy, iz = izmin + oz;

        float cxp = ((float)ix * 0.4f + (-40.f)) + 0.2f;
        float cyp = ((float)iy * 0.4f + (-40.f)) + 0.2f;
        float czp = ((float)iz * 0.4f + ( -4.f)) + 0.2f;

        float dx = cxp - mx, dy = cyp - my, dz = czp - mz;
        float maha = i00*dx*dx + i11*dy*dy + i22*dz*dz
                   + 2.f*(i01*dx*dy + i02*dx*dz + i12*dy*dz);
        // exp(-0.5*maha) = exp2(-0.5*log2(e)*maha)
        float w = op * exp2f(-0.72134752f * maha);

        int flat = (ix * GY + iy) * GZ + iz;
        atomicAdd(density + flat, w);
        float* fp = gfeat + (size_t)flat * NCH;
        red_add_v4(fp,     w*f0.x, w*f0.y, w*f0.z, w*f0.w);
        red_add_v4(fp + 4, w*f1.x, w*f1.y, w*f1.z, w*f1.w);
    }
}

// One thread per HALF-voxel (proven coalesced pattern). Reads scratch,
// writes normalized output to d_out, and RE-ZEROES scratch (restoring the
// invariant for the next launch / graph replay).
__global__ __launch_bounds__(256) void finalize_kernel(float* __restrict__ out_density,
                                                        float4* __restrict__ out_gfeat4) {
    int i = blockIdx.x * blockDim.x + threadIdx.x;
    if (i >= NVOX * 2) return;
    int v = i >> 1;

    float*  scr_d  = g_scr;
    float4* scr_g4 = (float4*)(g_scr + NVOX);

    float  d = scr_d[v];
    float4 x = scr_g4[i];

    float inv = 1.0f / fmaxf(d, 1e-6f);
    x.x *= inv; x.y *= inv; x.z *= inv; x.w *= inv;
    out_gfeat4[i] = x;
    scr_g4[i] = make_float4(0.f, 0.f, 0.f, 0.f);

    if ((i & 1) == 0) {          // one thread per voxel handles density
        out_density[v] = d;
        scr_d[v] = 0.f;
    }
}

extern "C" void kernel_launch(void* const* d_in, const int* in_sizes, int n_in,
                              void* d_out, int out_size) {
    const float* means  = (const float*)d_in[0];
    const float* opac   = (const float*)d_in[1];
    const float* scales = (const float*)d_in[2];
    const float* rots   = (const float*)d_in[3];
    const float* feats  = (const float*)d_in[4];

    float* density = (float*)d_out;
    float* gfeat   = density + NVOX;

    int N = in_sizes[1];  // opacities: B*N*1 elements

    // No memset: g_scr starts zeroed (module load) and finalize_kernel
    // re-zeroes it each launch.

    int threads = N * 32;  // one warp per Gaussian
    vox_kernel<<<(threads + 255) / 256, 256>>>(means, opac, scales, rots, feats, N);

    int nhalf = NVOX * 2;
    finalize_kernel<<<(nhalf + 255) / 256, 256>>>(density, (float4*)gfeat);
}